// round 14
// baseline (speedup 1.0000x reference)
#include <cuda_runtime.h>
#include <math.h>

#define HW 16384     // 128*128 spatial
#define TS 64        // spatial tile per block

// Innermost 32x32 matrices for the size-64 symmetric split, [i][n], i,n in [0,32)
__device__ float g_Me[32 * 32];
__device__ float g_Mo[32 * 32];

__global__ void init_coeffs() {
    int idx = blockIdx.x * 256 + threadIdx.x;   // 0..1023 (4 blocks x 256)
    int i = idx >> 5;
    int n = idx & 31;
    float t = (float)(2 * n + 1);
    g_Me[idx] = (i == 0) ? 1.0f
                         : 2.0f * cospif((float)i * t * (1.0f / 64.0f));
    g_Mo[idx] = 2.0f * cospif((float)(2 * i + 1) * t * (1.0f / 128.0f));
}

// Level-3 Lee iDCT, 4x4 micro-tile, 128 threads/CTA, 3 CTAs/SM.
// k-loop split into two 4-GEMM groups to cap live registers at ~165.
__global__ __launch_bounds__(128, 3) void idct_lee3(const float* __restrict__ ip,
                                                    float* __restrict__ out) {
    extern __shared__ float sm[];
    float* sMe  = sm;              // 1024 floats
    float* sMo  = sm + 1024;       // 1024
    float* sUe  = sm + 2048;       // each buffer [i][s] 32x64 = 2048 floats
    float* sUo  = sm + 4096;
    float* sGue = sm + 6144;
    float* sGuo = sm + 8192;
    float* sPe  = sm + 10240;
    float* sPo  = sm + 12288;
    float* sGpe = sm + 14336;
    float* sGpo = sm + 16384;      // total 18432 floats = 72 KB

    const int b  = blockIdx.x >> 8;
    const int st = blockIdx.x & 255;
    const int s0 = st * TS;
    const int tid = threadIdx.x;
    const int tn = tid >> 4;       // 0..7  -> 4 n-rows each (n in [0,32))
    const int ts = tid & 15;       // 0..15 -> 4 spatial cols

    const float* xb = ip + (size_t)b * 256 * HW + s0;

    // ---- stage cosine matrices: 256 float4 each, 2 per thread ----
#pragma unroll
    for (int r = 0; r < 2; r++) {
        int off = (tid + r * 128) << 2;
        *(float4*)&sMe[off] = *(const float4*)&g_Me[off];
        *(float4*)&sMo[off] = *(const float4*)&g_Mo[off];
    }

    // ---- stage 8 input buffers: 512 float4 each, 4 rounds of 128 ----
#pragma unroll
    for (int r = 0; r < 4; r++) {
        int f4 = tid + r * 128;                 // 0..511
        int i  = f4 >> 4;                       // 0..31
        int sc = (f4 & 15) << 2;                // 0..60

        float4 c0 = *(const float4*)&xb[(size_t)(8 * i)     * HW + sc];
        float4 c1 = *(const float4*)&xb[(size_t)(8 * i + 1) * HW + sc];
        float4 c2 = *(const float4*)&xb[(size_t)(8 * i + 2) * HW + sc];
        float4 c3 = *(const float4*)&xb[(size_t)(8 * i + 3) * HW + sc];
        float4 c4 = *(const float4*)&xb[(size_t)(8 * i + 4) * HW + sc];
        float4 c5 = *(const float4*)&xb[(size_t)(8 * i + 5) * HW + sc];
        float4 c6 = *(const float4*)&xb[(size_t)(8 * i + 6) * HW + sc];
        float4 c7 = *(const float4*)&xb[(size_t)(8 * i + 7) * HW + sc];
        float4 m1 = make_float4(0.f, 0.f, 0.f, 0.f);
        float4 m2 = m1, m3 = m1;
        if (i > 0) {
            m1 = *(const float4*)&xb[(size_t)(8 * i - 1) * HW + sc];
            m2 = *(const float4*)&xb[(size_t)(8 * i - 2) * HW + sc];
            m3 = *(const float4*)&xb[(size_t)(8 * i - 3) * HW + sc];
        }

        int o = i * 64 + sc;
        *(float4*)&sUe[o] = c0;
        *(float4*)&sUo[o] = c4;
        float4 v;
        v.x = c2.x + m2.x; v.y = c2.y + m2.y; v.z = c2.z + m2.z; v.w = c2.w + m2.w;
        *(float4*)&sGue[o] = v;
        v.x = c6.x + c2.x; v.y = c6.y + c2.y; v.z = c6.z + c2.z; v.w = c6.w + c2.w;
        *(float4*)&sGuo[o] = v;
        v.x = c1.x + m1.x; v.y = c1.y + m1.y; v.z = c1.z + m1.z; v.w = c1.w + m1.w;
        *(float4*)&sPe[o] = v;
        v.x = c5.x + c3.x; v.y = c5.y + c3.y; v.z = c5.z + c3.z; v.w = c5.w + c3.w;
        *(float4*)&sPo[o] = v;
        v.x = (c3.x + c1.x) + (m1.x + m3.x);
        v.y = (c3.y + c1.y) + (m1.y + m3.y);
        v.z = (c3.z + c1.z) + (m1.z + m3.z);
        v.w = (c3.w + c1.w) + (m1.w + m3.w);
        *(float4*)&sGpe[o] = v;
        v.x = (c7.x + c5.x) + (c3.x + c1.x);
        v.y = (c7.y + c5.y) + (c3.y + c1.y);
        v.z = (c7.z + c5.z) + (c3.z + c1.z);
        v.w = (c7.w + c5.w) + (c3.w + c1.w);
        *(float4*)&sGpo[o] = v;
    }
    __syncthreads();

    float aPU[4][4], aQU[4][4], aPGU[4][4], aQGU[4][4];
    float aPP[4][4], aQP[4][4], aPGP[4][4], aQGP[4][4];
#pragma unroll
    for (int i = 0; i < 4; i++)
#pragma unroll
        for (int j = 0; j < 4; j++) {
            aPU[i][j] = 0.f; aQU[i][j] = 0.f; aPGU[i][j] = 0.f; aQGU[i][j] = 0.f;
            aPP[i][j] = 0.f; aQP[i][j] = 0.f; aPGP[i][j] = 0.f; aQGP[i][j] = 0.f;
        }

    const int nOff = tn * 4;
    const int sOff = ts * 4;

#pragma unroll 2
    for (int k = 0; k < 32; k++) {
        float4 me4 = *(float4*)&sMe[k * 32 + nOff];
        float4 mo4 = *(float4*)&sMo[k * 32 + nOff];
        float me[4] = {me4.x, me4.y, me4.z, me4.w};
        float mo[4] = {mo4.x, mo4.y, mo4.z, mo4.w};

        // ---- group 1: U family (4 GEMMs) ----
        {
            float4 v_ue  = *(float4*)&sUe [k * 64 + sOff];
            float4 v_uo  = *(float4*)&sUo [k * 64 + sOff];
            float4 v_gue = *(float4*)&sGue[k * 64 + sOff];
            float4 v_guo = *(float4*)&sGuo[k * 64 + sOff];
            float ue[4]  = {v_ue.x,  v_ue.y,  v_ue.z,  v_ue.w};
            float uo[4]  = {v_uo.x,  v_uo.y,  v_uo.z,  v_uo.w};
            float gue[4] = {v_gue.x, v_gue.y, v_gue.z, v_gue.w};
            float guo[4] = {v_guo.x, v_guo.y, v_guo.z, v_guo.w};
#pragma unroll
            for (int i = 0; i < 4; i++) {
#pragma unroll
                for (int j = 0; j < 4; j++) {
                    aPU [i][j] = fmaf(me[i], ue[j],  aPU [i][j]);
                    aQU [i][j] = fmaf(mo[i], uo[j],  aQU [i][j]);
                    aPGU[i][j] = fmaf(me[i], gue[j], aPGU[i][j]);
                    aQGU[i][j] = fmaf(mo[i], guo[j], aQGU[i][j]);
                }
            }
        }
        // ---- group 2: P family (4 GEMMs) ----
        {
            float4 v_pe  = *(float4*)&sPe [k * 64 + sOff];
            float4 v_po  = *(float4*)&sPo [k * 64 + sOff];
            float4 v_gpe = *(float4*)&sGpe[k * 64 + sOff];
            float4 v_gpo = *(float4*)&sGpo[k * 64 + sOff];
            float pe[4]  = {v_pe.x,  v_pe.y,  v_pe.z,  v_pe.w};
            float po[4]  = {v_po.x,  v_po.y,  v_po.z,  v_po.w};
            float gpe[4] = {v_gpe.x, v_gpe.y, v_gpe.z, v_gpe.w};
            float gpo[4] = {v_gpo.x, v_gpo.y, v_gpo.z, v_gpo.w};
#pragma unroll
            for (int i = 0; i < 4; i++) {
#pragma unroll
                for (int j = 0; j < 4; j++) {
                    aPP [i][j] = fmaf(me[i], pe[j],  aPP [i][j]);
                    aQP [i][j] = fmaf(mo[i], po[j],  aQP [i][j]);
                    aPGP[i][j] = fmaf(me[i], gpe[j], aPGP[i][j]);
                    aQGP[i][j] = fmaf(mo[i], gpo[j], aQGP[i][j]);
                }
            }
        }
    }

    // ---- epilogue ----
    float4 gu0f = *(float4*)&sGue[sOff];   // gu[0] = x[2]
    float4 gp0f = *(float4*)&sGpe[sOff];   // gp[0] = x[3]+x[1]
    float4 h0f  = *(float4*)&sPe[sOff];    // h[0]  = x[1]
    float gu0[4] = {gu0f.x, gu0f.y, gu0f.z, gu0f.w};
    float gp0[4] = {gp0f.x, gp0f.y, gp0f.z, gp0f.w};
    float h0[4]  = {h0f.x,  h0f.y,  h0f.z,  h0f.w};

    float* ob = out + (size_t)b * 256 * HW + s0 + sOff;

#pragma unroll
    for (int i = 0; i < 4; i++) {
        int n  = nOff + i;        // 0..31
        int na = n;
        int nb = 63 - n;
        float icA = 0.5f / cospif((float)(2 * na + 1) * (1.0f / 256.0f));
        float icB = 0.5f / cospif((float)(2 * nb + 1) * (1.0f / 256.0f));

        int   m2r[4] = {na, 127 - na, nb, 127 - nb};
        float ic3[4];
#pragma unroll
        for (int q = 0; q < 4; q++)
            ic3[q] = 0.5f / cospif((float)(2 * m2r[q] + 1) * (1.0f / 512.0f));

        float4 ro[4], rp[4];
        float* pro[4] = {(float*)&ro[0], (float*)&ro[1], (float*)&ro[2], (float*)&ro[3]};
        float* prp[4] = {(float*)&rp[0], (float*)&rp[1], (float*)&rp[2], (float*)&rp[3]};

#pragma unroll
        for (int j = 0; j < 4; j++) {
            float AUa  = aPU [i][j] + aQU [i][j],  AUb  = aPU [i][j] - aQU [i][j];
            float AGUa = aPGU[i][j] + aQGU[i][j],  AGUb = aPGU[i][j] - aQGU[i][j];
            float APa  = aPP [i][j] + aQP [i][j],  APb  = aPP [i][j] - aQP [i][j];
            float AGPa = aPGP[i][j] + aQGP[i][j],  AGPb = aPGP[i][j] - aQGP[i][j];

            float q2ea = (AGUa + gu0[j]) * icA;
            float q2eb = (AGUb + gu0[j]) * icB;
            float q2ha = (AGPa + gp0[j]) * icA;
            float q2hb = (AGPb + gp0[j]) * icB;
            float E[4], Hh[4];
            E[0]  = AUa + q2ea;  E[1]  = AUa - q2ea;
            E[2]  = AUb + q2eb;  E[3]  = AUb - q2eb;
            Hh[0] = APa + q2ha;  Hh[1] = APa - q2ha;
            Hh[2] = APb + q2hb;  Hh[3] = APb - q2hb;

#pragma unroll
            for (int q = 0; q < 4; q++) {
                float q3 = (Hh[q] + h0[j]) * ic3[q];
                pro[q][j] = E[q] + q3;
                prp[q][j] = E[q] - q3;
            }
        }

#pragma unroll
        for (int q = 0; q < 4; q++) {
            *(float4*)&ob[(size_t)m2r[q] * HW]         = ro[q];
            *(float4*)&ob[(size_t)(255 - m2r[q]) * HW] = rp[q];
        }
    }
}

extern "C" void kernel_launch(void* const* d_in, const int* in_sizes, int n_in,
                              void* d_out, int out_size) {
    const float* ip = (const float*)d_in[0];
    float* out = (float*)d_out;
    (void)in_sizes; (void)n_in; (void)out_size;

    cudaFuncSetAttribute(idct_lee3, cudaFuncAttributeMaxDynamicSharedMemorySize,
                         72 * 1024);

    init_coeffs<<<4, 256>>>();
    idct_lee3<<<8 * 256, 128, 72 * 1024>>>(ip, out);
}

// round 15
// speedup vs baseline: 1.1098x; 1.1098x over previous
#include <cuda_runtime.h>
#include <math.h>

#define HW 16384     // 128*128 spatial
#define TS 64        // spatial tile per block

__device__ float g_Me[32 * 32];
__device__ float g_Mo[32 * 32];

__global__ void init_coeffs() {
    int idx = blockIdx.x * 256 + threadIdx.x;   // 0..1023 (4 blocks x 256)
    int i = idx >> 5;
    int n = idx & 31;
    float t = (float)(2 * n + 1);
    g_Me[idx] = (i == 0) ? 1.0f
                         : 2.0f * cospif((float)i * t * (1.0f / 64.0f));
    g_Mo[idx] = 2.0f * cospif((float)(2 * i + 1) * t * (1.0f / 128.0f));
}

__device__ __forceinline__ float4 f4add(float4 a, float4 b) {
    return make_float4(a.x + b.x, a.y + b.y, a.z + b.z, a.w + b.w);
}

// Write the 8 combined buffers for global row i (smem offset o = i*64+sc).
__device__ __forceinline__ void store_combos(float* sm, int o,
    float4 c0, float4 c1, float4 c2, float4 c3,
    float4 c4, float4 c5, float4 c6, float4 c7,
    float4 m1, float4 m2, float4 m3)
{
    float* sUe  = sm + 2048;
    float* sUo  = sm + 4096;
    float* sGue = sm + 6144;
    float* sGuo = sm + 8192;
    float* sPe  = sm + 10240;
    float* sPo  = sm + 12288;
    float* sGpe = sm + 14336;
    float* sGpo = sm + 16384;
    *(float4*)&sUe[o]  = c0;
    *(float4*)&sUo[o]  = c4;
    *(float4*)&sGue[o] = f4add(c2, m2);
    *(float4*)&sGuo[o] = f4add(c6, c2);
    *(float4*)&sPe[o]  = f4add(c1, m1);
    *(float4*)&sPo[o]  = f4add(c5, c3);
    *(float4*)&sGpe[o] = f4add(f4add(c3, c1), f4add(m1, m3));
    *(float4*)&sGpo[o] = f4add(f4add(c7, c5), f4add(c3, c1));
}

// Level-3 Lee iDCT, 4x4 micro-tile, 128 threads/CTA, 2 CTAs/SM.
// k-loop pipelined in 4 chunks of 8 rows: LDG prefetch of chunk c+1 overlaps
// FFMA compute of chunk c (disjoint smem regions, no double buffer needed).
__global__ __launch_bounds__(128, 2) void idct_lee3(const float* __restrict__ ip,
                                                    float* __restrict__ out) {
    extern __shared__ float sm[];
    float* sMe  = sm;              // 1024 floats
    float* sMo  = sm + 1024;       // 1024
    float* sUe  = sm + 2048;       // each buffer [i][s] 32x64 = 2048 floats
    float* sUo  = sm + 4096;
    float* sGue = sm + 6144;
    float* sGuo = sm + 8192;
    float* sPe  = sm + 10240;
    float* sPo  = sm + 12288;
    float* sGpe = sm + 14336;
    float* sGpo = sm + 16384;      // total 18432 floats = 72 KB

    const int b  = blockIdx.x >> 8;
    const int st = blockIdx.x & 255;
    const int s0 = st * TS;
    const int tid = threadIdx.x;
    const int tn  = tid >> 4;      // 0..7  (also local staging row)
    const int ts  = tid & 15;      // 0..15

    const float* xb = ip + (size_t)b * 256 * HW + s0;
    const int scs = ts << 2;       // spatial float offset 0..60

    // ---- stage cosine matrices ----
#pragma unroll
    for (int r = 0; r < 2; r++) {
        int off = (tid + r * 128) << 2;
        *(float4*)&sMe[off] = *(const float4*)&g_Me[off];
        *(float4*)&sMo[off] = *(const float4*)&g_Mo[off];
    }

    // ---- stage chunk 0 (rows i = 0..7), boundary-aware ----
    {
        int i = tn;                               // 0..7
        const float* rb = xb + (size_t)(8 * i) * HW + scs;
        float4 c0 = *(const float4*)&rb[0 * HW];
        float4 c1 = *(const float4*)&rb[1 * HW];
        float4 c2 = *(const float4*)&rb[2 * HW];
        float4 c3 = *(const float4*)&rb[3 * HW];
        float4 c4 = *(const float4*)&rb[4 * HW];
        float4 c5 = *(const float4*)&rb[5 * HW];
        float4 c6 = *(const float4*)&rb[6 * HW];
        float4 c7 = *(const float4*)&rb[7 * HW];
        float4 m1 = make_float4(0.f, 0.f, 0.f, 0.f);
        float4 m2 = m1, m3 = m1;
        if (i > 0) {
            m1 = *(const float4*)&rb[-1 * HW];
            m2 = *(const float4*)&rb[-2 * HW];
            m3 = *(const float4*)&rb[-3 * HW];
        }
        store_combos(sm, i * 64 + scs, c0, c1, c2, c3, c4, c5, c6, c7, m1, m2, m3);
    }
    __syncthreads();

    float aPU[4][4], aQU[4][4], aPGU[4][4], aQGU[4][4];
    float aPP[4][4], aQP[4][4], aPGP[4][4], aQGP[4][4];
#pragma unroll
    for (int i = 0; i < 4; i++)
#pragma unroll
        for (int j = 0; j < 4; j++) {
            aPU[i][j] = 0.f; aQU[i][j] = 0.f; aPGU[i][j] = 0.f; aQGU[i][j] = 0.f;
            aPP[i][j] = 0.f; aQP[i][j] = 0.f; aPGP[i][j] = 0.f; aQGP[i][j] = 0.f;
        }

    const int nOff = tn * 4;
    const int sOff = scs;

    // ---- pipelined main loop: 4 chunks of 8 k's ----
#pragma unroll
    for (int c = 0; c < 4; c++) {
        // prefetch chunk c+1 (rows >= 8, no boundary) into registers
        float4 p0, p1, p2, p3, p4, p5, p6, p7, q1, q2, q3;
        if (c < 3) {
            int i = 8 * (c + 1) + tn;
            const float* rb = xb + (size_t)(8 * i) * HW + scs;
            p0 = *(const float4*)&rb[0 * HW];
            p1 = *(const float4*)&rb[1 * HW];
            p2 = *(const float4*)&rb[2 * HW];
            p3 = *(const float4*)&rb[3 * HW];
            p4 = *(const float4*)&rb[4 * HW];
            p5 = *(const float4*)&rb[5 * HW];
            p6 = *(const float4*)&rb[6 * HW];
            p7 = *(const float4*)&rb[7 * HW];
            q1 = *(const float4*)&rb[-1 * HW];
            q2 = *(const float4*)&rb[-2 * HW];
            q3 = *(const float4*)&rb[-3 * HW];
        }

        // compute chunk c
#pragma unroll 2
        for (int kk = 0; kk < 8; kk++) {
            int k = 8 * c + kk;
            float4 me4 = *(float4*)&sMe[k * 32 + nOff];
            float4 mo4 = *(float4*)&sMo[k * 32 + nOff];
            float me[4] = {me4.x, me4.y, me4.z, me4.w};
            float mo[4] = {mo4.x, mo4.y, mo4.z, mo4.w};

            {   // U family
                float4 v_ue  = *(float4*)&sUe [k * 64 + sOff];
                float4 v_uo  = *(float4*)&sUo [k * 64 + sOff];
                float4 v_gue = *(float4*)&sGue[k * 64 + sOff];
                float4 v_guo = *(float4*)&sGuo[k * 64 + sOff];
                float ue[4]  = {v_ue.x,  v_ue.y,  v_ue.z,  v_ue.w};
                float uo[4]  = {v_uo.x,  v_uo.y,  v_uo.z,  v_uo.w};
                float gue[4] = {v_gue.x, v_gue.y, v_gue.z, v_gue.w};
                float guo[4] = {v_guo.x, v_guo.y, v_guo.z, v_guo.w};
#pragma unroll
                for (int i = 0; i < 4; i++)
#pragma unroll
                    for (int j = 0; j < 4; j++) {
                        aPU [i][j] = fmaf(me[i], ue[j],  aPU [i][j]);
                        aQU [i][j] = fmaf(mo[i], uo[j],  aQU [i][j]);
                        aPGU[i][j] = fmaf(me[i], gue[j], aPGU[i][j]);
                        aQGU[i][j] = fmaf(mo[i], guo[j], aQGU[i][j]);
                    }
            }
            {   // P family
                float4 v_pe  = *(float4*)&sPe [k * 64 + sOff];
                float4 v_po  = *(float4*)&sPo [k * 64 + sOff];
                float4 v_gpe = *(float4*)&sGpe[k * 64 + sOff];
                float4 v_gpo = *(float4*)&sGpo[k * 64 + sOff];
                float pe[4]  = {v_pe.x,  v_pe.y,  v_pe.z,  v_pe.w};
                float po[4]  = {v_po.x,  v_po.y,  v_po.z,  v_po.w};
                float gpe[4] = {v_gpe.x, v_gpe.y, v_gpe.z, v_gpe.w};
                float gpo[4] = {v_gpo.x, v_gpo.y, v_gpo.z, v_gpo.w};
#pragma unroll
                for (int i = 0; i < 4; i++)
#pragma unroll
                    for (int j = 0; j < 4; j++) {
                        aPP [i][j] = fmaf(me[i], pe[j],  aPP [i][j]);
                        aQP [i][j] = fmaf(mo[i], po[j],  aQP [i][j]);
                        aPGP[i][j] = fmaf(me[i], gpe[j], aPGP[i][j]);
                        aQGP[i][j] = fmaf(mo[i], gpo[j], aQGP[i][j]);
                    }
            }
        }

        // commit prefetched chunk to smem (disjoint rows -> only one barrier)
        if (c < 3) {
            int i = 8 * (c + 1) + tn;
            store_combos(sm, i * 64 + scs, p0, p1, p2, p3, p4, p5, p6, p7, q1, q2, q3);
            __syncthreads();
        }
    }

    // ---- epilogue (unchanged) ----
    float4 gu0f = *(float4*)&sGue[sOff];
    float4 gp0f = *(float4*)&sGpe[sOff];
    float4 h0f  = *(float4*)&sPe[sOff];
    float gu0[4] = {gu0f.x, gu0f.y, gu0f.z, gu0f.w};
    float gp0[4] = {gp0f.x, gp0f.y, gp0f.z, gp0f.w};
    float h0[4]  = {h0f.x,  h0f.y,  h0f.z,  h0f.w};

    float* ob = out + (size_t)b * 256 * HW + s0 + sOff;

#pragma unroll
    for (int i = 0; i < 4; i++) {
        int n  = nOff + i;
        int na = n;
        int nb = 63 - n;
        float icA = 0.5f / cospif((float)(2 * na + 1) * (1.0f / 256.0f));
        float icB = 0.5f / cospif((float)(2 * nb + 1) * (1.0f / 256.0f));

        int   m2r[4] = {na, 127 - na, nb, 127 - nb};
        float ic3[4];
#pragma unroll
        for (int q = 0; q < 4; q++)
            ic3[q] = 0.5f / cospif((float)(2 * m2r[q] + 1) * (1.0f / 512.0f));

        float4 ro[4], rp[4];
        float* pro[4] = {(float*)&ro[0], (float*)&ro[1], (float*)&ro[2], (float*)&ro[3]};
        float* prp[4] = {(float*)&rp[0], (float*)&rp[1], (float*)&rp[2], (float*)&rp[3]};

#pragma unroll
        for (int j = 0; j < 4; j++) {
            float AUa  = aPU [i][j] + aQU [i][j],  AUb  = aPU [i][j] - aQU [i][j];
            float AGUa = aPGU[i][j] + aQGU[i][j],  AGUb = aPGU[i][j] - aQGU[i][j];
            float APa  = aPP [i][j] + aQP [i][j],  APb  = aPP [i][j] - aQP [i][j];
            float AGPa = aPGP[i][j] + aQGP[i][j],  AGPb = aPGP[i][j] - aQGP[i][j];

            float q2ea = (AGUa + gu0[j]) * icA;
            float q2eb = (AGUb + gu0[j]) * icB;
            float q2ha = (AGPa + gp0[j]) * icA;
            float q2hb = (AGPb + gp0[j]) * icB;
            float E[4], Hh[4];
            E[0]  = AUa + q2ea;  E[1]  = AUa - q2ea;
            E[2]  = AUb + q2eb;  E[3]  = AUb - q2eb;
            Hh[0] = APa + q2ha;  Hh[1] = APa - q2ha;
            Hh[2] = APb + q2hb;  Hh[3] = APb - q2hb;

#pragma unroll
            for (int q = 0; q < 4; q++) {
                float q3 = (Hh[q] + h0[j]) * ic3[q];
                pro[q][j] = E[q] + q3;
                prp[q][j] = E[q] - q3;
            }
        }

#pragma unroll
        for (int q = 0; q < 4; q++) {
            *(float4*)&ob[(size_t)m2r[q] * HW]         = ro[q];
            *(float4*)&ob[(size_t)(255 - m2r[q]) * HW] = rp[q];
        }
    }
}

extern "C" void kernel_launch(void* const* d_in, const int* in_sizes, int n_in,
                              void* d_out, int out_size) {
    const float* ip = (const float*)d_in[0];
    float* out = (float*)d_out;
    (void)in_sizes; (void)n_in; (void)out_size;

    cudaFuncSetAttribute(idct_lee3, cudaFuncAttributeMaxDynamicSharedMemorySize,
                         72 * 1024);

    init_coeffs<<<4, 256>>>();
    idct_lee3<<<8 * 256, 128, 72 * 1024>>>(ip, out);
}

// round 17
// speedup vs baseline: 1.1847x; 1.0675x over previous
#include <cuda_runtime.h>
#include <math.h>

#define HW 16384     // 128*128 spatial
#define TS 64        // spatial tile per block

typedef unsigned long long ull;

__device__ float g_Me[32 * 32];
__device__ float g_Mo[32 * 32];

__global__ void init_coeffs() {
    int idx = blockIdx.x * 256 + threadIdx.x;   // 0..1023 (4 blocks x 256)
    int i = idx >> 5;
    int n = idx & 31;
    float t = (float)(2 * n + 1);
    g_Me[idx] = (i == 0) ? 1.0f
                         : 2.0f * cospif((float)i * t * (1.0f / 64.0f));
    g_Mo[idx] = 2.0f * cospif((float)(2 * i + 1) * t * (1.0f / 128.0f));
}

// packed fp32x2 fma: d = a*b + d   (both lanes)
__device__ __forceinline__ void fma2(ull& d, ull a, ull b) {
    asm("fma.rn.f32x2 %0, %1, %2, %0;" : "+l"(d) : "l"(a), "l"(b));
}
__device__ __forceinline__ ull pack2(float v) {
    ull r;
    asm("mov.b64 %0, {%1, %1};" : "=l"(r) : "f"(v));
    return r;
}
__device__ __forceinline__ void unpack2(float& lo, float& hi, ull v) {
    asm("mov.b64 {%0, %1}, %2;" : "=f"(lo), "=f"(hi) : "l"(v));
}

// Level-3 Lee iDCT, 4x4 micro-tile, 128 threads/CTA, 2 CTAs/SM.
// Inner product uses fma.rn.f32x2 (FFMA2): 2 FMA lanes per issue slot.
__global__ __launch_bounds__(128, 2) void idct_lee3(const float* __restrict__ ip,
                                                    float* __restrict__ out) {
    extern __shared__ float sm[];
    float* sMe  = sm;              // 1024 floats
    float* sMo  = sm + 1024;       // 1024
    float* sUe  = sm + 2048;       // each buffer [i][s] 32x64 = 2048 floats
    float* sUo  = sm + 4096;
    float* sGue = sm + 6144;
    float* sGuo = sm + 8192;
    float* sPe  = sm + 10240;
    float* sPo  = sm + 12288;
    float* sGpe = sm + 14336;
    float* sGpo = sm + 16384;      // total 18432 floats = 72 KB

    const int b  = blockIdx.x >> 8;
    const int st = blockIdx.x & 255;
    const int s0 = st * TS;
    const int tid = threadIdx.x;
    const int tn = tid >> 4;       // 0..7  -> 4 n-rows each (n in [0,32))
    const int ts = tid & 15;       // 0..15 -> 4 spatial cols

    const float* xb = ip + (size_t)b * 256 * HW + s0;

    // ---- stage cosine matrices: 256 float4 each, 2 per thread ----
#pragma unroll
    for (int r = 0; r < 2; r++) {
        int off = (tid + r * 128) << 2;
        *(float4*)&sMe[off] = *(const float4*)&g_Me[off];
        *(float4*)&sMo[off] = *(const float4*)&g_Mo[off];
    }

    // ---- stage 8 input buffers: 512 float4 each, 4 rounds of 128 ----
#pragma unroll
    for (int r = 0; r < 4; r++) {
        int f4 = tid + r * 128;                 // 0..511
        int i  = f4 >> 4;                       // 0..31
        int sc = (f4 & 15) << 2;                // 0..60

        float4 c0 = *(const float4*)&xb[(size_t)(8 * i)     * HW + sc];
        float4 c1 = *(const float4*)&xb[(size_t)(8 * i + 1) * HW + sc];
        float4 c2 = *(const float4*)&xb[(size_t)(8 * i + 2) * HW + sc];
        float4 c3 = *(const float4*)&xb[(size_t)(8 * i + 3) * HW + sc];
        float4 c4 = *(const float4*)&xb[(size_t)(8 * i + 4) * HW + sc];
        float4 c5 = *(const float4*)&xb[(size_t)(8 * i + 5) * HW + sc];
        float4 c6 = *(const float4*)&xb[(size_t)(8 * i + 6) * HW + sc];
        float4 c7 = *(const float4*)&xb[(size_t)(8 * i + 7) * HW + sc];
        float4 m1 = make_float4(0.f, 0.f, 0.f, 0.f);
        float4 m2 = m1, m3 = m1;
        if (i > 0) {
            m1 = *(const float4*)&xb[(size_t)(8 * i - 1) * HW + sc];
            m2 = *(const float4*)&xb[(size_t)(8 * i - 2) * HW + sc];
            m3 = *(const float4*)&xb[(size_t)(8 * i - 3) * HW + sc];
        }

        int o = i * 64 + sc;
        *(float4*)&sUe[o] = c0;
        *(float4*)&sUo[o] = c4;
        float4 v;
        v.x = c2.x + m2.x; v.y = c2.y + m2.y; v.z = c2.z + m2.z; v.w = c2.w + m2.w;
        *(float4*)&sGue[o] = v;
        v.x = c6.x + c2.x; v.y = c6.y + c2.y; v.z = c6.z + c2.z; v.w = c6.w + c2.w;
        *(float4*)&sGuo[o] = v;
        v.x = c1.x + m1.x; v.y = c1.y + m1.y; v.z = c1.z + m1.z; v.w = c1.w + m1.w;
        *(float4*)&sPe[o] = v;
        v.x = c5.x + c3.x; v.y = c5.y + c3.y; v.z = c5.z + c3.z; v.w = c5.w + c3.w;
        *(float4*)&sPo[o] = v;
        v.x = (c3.x + c1.x) + (m1.x + m3.x);
        v.y = (c3.y + c1.y) + (m1.y + m3.y);
        v.z = (c3.z + c1.z) + (m1.z + m3.z);
        v.w = (c3.w + c1.w) + (m1.w + m3.w);
        *(float4*)&sGpe[o] = v;
        v.x = (c7.x + c5.x) + (c3.x + c1.x);
        v.y = (c7.y + c5.y) + (c3.y + c1.y);
        v.z = (c7.z + c5.z) + (c3.z + c1.z);
        v.w = (c7.w + c5.w) + (c3.w + c1.w);
        *(float4*)&sGpo[o] = v;
    }
    __syncthreads();

    // packed accumulators: [i][pair], pair 0 = cols {0,1}, pair 1 = cols {2,3}
    ull aPU[4][2], aQU[4][2], aPGU[4][2], aQGU[4][2];
    ull aPP[4][2], aQP[4][2], aPGP[4][2], aQGP[4][2];
#pragma unroll
    for (int i = 0; i < 4; i++)
#pragma unroll
        for (int j = 0; j < 2; j++) {
            aPU[i][j] = 0ull; aQU[i][j] = 0ull; aPGU[i][j] = 0ull; aQGU[i][j] = 0ull;
            aPP[i][j] = 0ull; aQP[i][j] = 0ull; aPGP[i][j] = 0ull; aQGP[i][j] = 0ull;
        }

    const int nOff = tn * 4;
    const int sOff = ts * 4;

#pragma unroll 2
    for (int k = 0; k < 32; k++) {
        float4 me4 = *(float4*)&sMe[k * 32 + nOff];
        float4 mo4 = *(float4*)&sMo[k * 32 + nOff];
        ull me2[4] = {pack2(me4.x), pack2(me4.y), pack2(me4.z), pack2(me4.w)};
        ull mo2[4] = {pack2(mo4.x), pack2(mo4.y), pack2(mo4.z), pack2(mo4.w)};

        ulonglong2 v_ue  = *(ulonglong2*)&sUe [k * 64 + sOff];
        ulonglong2 v_uo  = *(ulonglong2*)&sUo [k * 64 + sOff];
        ulonglong2 v_gue = *(ulonglong2*)&sGue[k * 64 + sOff];
        ulonglong2 v_guo = *(ulonglong2*)&sGuo[k * 64 + sOff];
        ulonglong2 v_pe  = *(ulonglong2*)&sPe [k * 64 + sOff];
        ulonglong2 v_po  = *(ulonglong2*)&sPo [k * 64 + sOff];
        ulonglong2 v_gpe = *(ulonglong2*)&sGpe[k * 64 + sOff];
        ulonglong2 v_gpo = *(ulonglong2*)&sGpo[k * 64 + sOff];

#pragma unroll
        for (int i = 0; i < 4; i++) {
            fma2(aPU [i][0], me2[i], v_ue.x);  fma2(aPU [i][1], me2[i], v_ue.y);
            fma2(aQU [i][0], mo2[i], v_uo.x);  fma2(aQU [i][1], mo2[i], v_uo.y);
            fma2(aPGU[i][0], me2[i], v_gue.x); fma2(aPGU[i][1], me2[i], v_gue.y);
            fma2(aQGU[i][0], mo2[i], v_guo.x); fma2(aQGU[i][1], mo2[i], v_guo.y);
            fma2(aPP [i][0], me2[i], v_pe.x);  fma2(aPP [i][1], me2[i], v_pe.y);
            fma2(aQP [i][0], mo2[i], v_po.x);  fma2(aQP [i][1], mo2[i], v_po.y);
            fma2(aPGP[i][0], me2[i], v_gpe.x); fma2(aPGP[i][1], me2[i], v_gpe.y);
            fma2(aQGP[i][0], mo2[i], v_gpo.x); fma2(aQGP[i][1], mo2[i], v_gpo.y);
        }
    }

    // ---- unpack accumulators to scalars ----
    float sPUv[4][4], sQUv[4][4], sPGUv[4][4], sQGUv[4][4];
    float sPPv[4][4], sQPv[4][4], sPGPv[4][4], sQGPv[4][4];
#pragma unroll
    for (int i = 0; i < 4; i++) {
#pragma unroll
        for (int j = 0; j < 2; j++) {
            unpack2(sPUv [i][2*j], sPUv [i][2*j+1], aPU [i][j]);
            unpack2(sQUv [i][2*j], sQUv [i][2*j+1], aQU [i][j]);
            unpack2(sPGUv[i][2*j], sPGUv[i][2*j+1], aPGU[i][j]);
            unpack2(sQGUv[i][2*j], sQGUv[i][2*j+1], aQGU[i][j]);
            unpack2(sPPv [i][2*j], sPPv [i][2*j+1], aPP [i][j]);
            unpack2(sQPv [i][2*j], sQPv [i][2*j+1], aQP [i][j]);
            unpack2(sPGPv[i][2*j], sPGPv[i][2*j+1], aPGP[i][j]);
            unpack2(sQGPv[i][2*j], sQGPv[i][2*j+1], aQGP[i][j]);
        }
    }

    // ---- epilogue ----
    float4 gu0f = *(float4*)&sGue[sOff];   // gu[0] = x[2]
    float4 gp0f = *(float4*)&sGpe[sOff];   // gp[0] = x[3]+x[1]
    float4 h0f  = *(float4*)&sPe[sOff];    // h[0]  = x[1]
    float gu0[4] = {gu0f.x, gu0f.y, gu0f.z, gu0f.w};
    float gp0[4] = {gp0f.x, gp0f.y, gp0f.z, gp0f.w};
    float h0[4]  = {h0f.x,  h0f.y,  h0f.z,  h0f.w};

    float* ob = out + (size_t)b * 256 * HW + s0 + sOff;

#pragma unroll
    for (int i = 0; i < 4; i++) {
        int n  = nOff + i;        // 0..31
        int na = n;
        int nb = 63 - n;
        float icA = 0.5f / cospif((float)(2 * na + 1) * (1.0f / 256.0f));
        float icB = 0.5f / cospif((float)(2 * nb + 1) * (1.0f / 256.0f));

        int   m2r[4] = {na, 127 - na, nb, 127 - nb};
        float ic3[4];
#pragma unroll
        for (int q = 0; q < 4; q++)
            ic3[q] = 0.5f / cospif((float)(2 * m2r[q] + 1) * (1.0f / 512.0f));

        float4 ro[4], rp[4];
        float* pro[4] = {(float*)&ro[0], (float*)&ro[1], (float*)&ro[2], (float*)&ro[3]};
        float* prp[4] = {(float*)&rp[0], (float*)&rp[1], (float*)&rp[2], (float*)&rp[3]};

#pragma unroll
        for (int j = 0; j < 4; j++) {
            float AUa  = sPUv [i][j] + sQUv [i][j],  AUb  = sPUv [i][j] - sQUv [i][j];
            float AGUa = sPGUv[i][j] + sQGUv[i][j],  AGUb = sPGUv[i][j] - sQGUv[i][j];
            float APa  = sPPv [i][j] + sQPv [i][j],  APb  = sPPv [i][j] - sQPv [i][j];
            float AGPa = sPGPv[i][j] + sQGPv[i][j],  AGPb = sPGPv[i][j] - sQGPv[i][j];

            float q2ea = (AGUa + gu0[j]) * icA;
            float q2eb = (AGUb + gu0[j]) * icB;
            float q2ha = (AGPa + gp0[j]) * icA;
            float q2hb = (AGPb + gp0[j]) * icB;
            float E[4], Hh[4];
            E[0]  = AUa + q2ea;  E[1]  = AUa - q2ea;
            E[2]  = AUb + q2eb;  E[3]  = AUb - q2eb;
            Hh[0] = APa + q2ha;  Hh[1] = APa - q2ha;
            Hh[2] = APb + q2hb;  Hh[3] = APb - q2hb;

#pragma unroll
            for (int q = 0; q < 4; q++) {
                float q3 = (Hh[q] + h0[j]) * ic3[q];
                pro[q][j] = E[q] + q3;
                prp[q][j] = E[q] - q3;
            }
        }

#pragma unroll
        for (int q = 0; q < 4; q++) {
            *(float4*)&ob[(size_t)m2r[q] * HW]         = ro[q];
            *(float4*)&ob[(size_t)(255 - m2r[q]) * HW] = rp[q];
        }
    }
}

extern "C" void kernel_launch(void* const* d_in, const int* in_sizes, int n_in,
                              void* d_out, int out_size) {
    const float* ip = (const float*)d_in[0];
    float* out = (float*)d_out;
    (void)in_sizes; (void)n_in; (void)out_size;

    cudaFuncSetAttribute(idct_lee3, cudaFuncAttributeMaxDynamicSharedMemorySize,
                         72 * 1024);

    init_coeffs<<<4, 256>>>();
    idct_lee3<<<8 * 256, 128, 72 * 1024>>>(ip, out);
}